// round 12
// baseline (speedup 1.0000x reference)
#include <cuda_runtime.h>
#include <cuda_fp16.h>
#include <cstdint>

// Problem constants (fixed by the reference: LENGTHS[i] = 1024 + 128*i, B=16)
#define T_TOK   31744
#define PREV    768
#define DIM     256
#define NDOCS   16
#define MAXLEN  2944

// GEMM tiling: CTA 64x256, 8 warps as 2(M) x 4(N), warp tile 32x64, fp16 k16
#define BM 64
#define BN 256
#define BK 64
#define NTHREADS 256
#define KTILES (PREV / BK)             // 12

// smem stages (u32 elements)
#define A_STAGE 4096                   // 64x64 fp32, chunk-permuted = 16 KB
#define B_STAGE 8192                   // 64x256 fp16 fragment-major = 32 KB
#define SMEM_BYTES ((2 * A_STAGE + 2 * B_STAGE) * 4)   // 98304 B -> 2 CTAs/SM

#define GRID_GEMM (T_TOK / BM)         // 496
#define PAD_ROWS  (NDOCS * MAXLEN - T_TOK)  // 15360
#define ZBLOCKS   120
#define ROWS_PER_Z (PAD_ROWS / ZBLOCKS)     // 128

// W pre-converted to fp16, fragment-major per 64-k tile (16384 halves/tile)
__device__ uint16_t g_WH[PREV * DIM];

// ---------------- helpers ----------------
__device__ __forceinline__ int doc_offset(int b) { return 1024 * b + 64 * b * (b - 1); }
__device__ __forceinline__ int pad_offset(int b) { return 1920 * b - 64 * b * (b - 1); }

__device__ __forceinline__ int out_row_for_token(int t) {
    int b = 0;
#pragma unroll
    for (int i = 1; i < NDOCS; ++i) if (t >= doc_offset(i)) b = i;
    return b * MAXLEN + (t - doc_offset(b));
}
__device__ __forceinline__ int out_row_for_pad(int p) {
    int b = 0;
#pragma unroll
    for (int i = 1; i < NDOCS; ++i) if (p >= pad_offset(i)) b = i;
    return b * MAXLEN + (1024 + 128 * b) + (p - pad_offset(b));
}

__device__ __forceinline__ uint32_t smem_u32_addr(const void* p) {
    uint32_t a;
    asm("{ .reg .u64 t; cvta.to.shared.u64 t, %1; cvt.u32.u64 %0, t; }" : "=r"(a) : "l"(p));
    return a;
}

__device__ __forceinline__ void mma_f16(float* d, const uint32_t* a, const uint32_t* b) {
    asm volatile(
        "mma.sync.aligned.m16n8k16.row.col.f32.f16.f16.f32 "
        "{%0,%1,%2,%3}, {%4,%5,%6,%7}, {%8,%9}, {%0,%1,%2,%3};"
        : "+f"(d[0]), "+f"(d[1]), "+f"(d[2]), "+f"(d[3])
        : "r"(a[0]), "r"(a[1]), "r"(a[2]), "r"(a[3]), "r"(b[0]), "r"(b[1]));
}

#define CP_ASYNC16(dst_u32, src_ptr) \
    asm volatile("cp.async.cg.shared.global [%0], [%1], 16;" \
                 :: "r"(dst_u32), "l"(src_ptr) : "memory")
#define CP_COMMIT() asm volatile("cp.async.commit_group;" ::: "memory")
#define CP_WAIT0()  asm volatile("cp.async.wait_group 0;" ::: "memory")

__device__ __forceinline__ uint32_t h2_to_u32(float x, float y) {
    __half2 h = __float22half2_rn(make_float2(x, y));
    return *reinterpret_cast<uint32_t*>(&h);
}

// B fragment-major HALF index within one 64x256 K-tile (16384 halves)
__host__ __device__ __forceinline__ int b_frag_half(int n, int kl) {
    int warpN = n >> 6, ni = (n >> 3) & 7, gid = n & 7;
    int kk = kl >> 4, k16 = kl & 15;
    int reg = k16 >> 3, t4 = (k16 & 7) >> 1, half = k16 & 1;
    int u32idx = ((((kk * 4 + warpN) * 8 + ni) * 8 + gid) * 4 + t4) * 2 + reg;
    return u32idx * 2 + half;
}

// A chunk-permuted dst (u32 index) for 16B chunk c (=4 floats k=4c..4c+3) of row:
//   kk=c>>2, kh=(c>>1)&1, tp=c&1; chunk idx = ((kk*2+kh)*64+row)*2+tp
__device__ __forceinline__ int a_chunk_u32(int row, int c) {
    int kk = c >> 2, kh = (c >> 1) & 1, tp = c & 1;
    return ((((kk * 2 + kh) * 64 + row) * 2 + tp)) * 4;
}

// ---------------- W convert + permute kernel (tiny, one-time) ----------------
__global__ void round_w_kernel(const float* __restrict__ W) {
    int i = blockIdx.x * 256 + threadIdx.x;     // over PREV*DIM
    int k = i / DIM, n = i - k * DIM;
    int kt = k >> 6, kl = k & 63;
    __half h = __float2half_rn(W[i]);
    g_WH[kt * (2 * B_STAGE) + b_frag_half(n, kl)] = __half_as_ushort(h);
}

// ---------------- main fused kernel ----------------
__global__ __launch_bounds__(NTHREADS, 2)
void gemm_tc_scatter_kernel(const float* __restrict__ A,
                            const float* __restrict__ bias,
                            float* __restrict__ out) {
    extern __shared__ uint32_t sm[];
    uint32_t* AsBase = sm;                    // [2][A_STAGE] fp32 chunk-permuted
    uint32_t* BsBase = sm + 2 * A_STAGE;      // [2][B_STAGE] fp16 fragment-major

    const int tid = threadIdx.x;
    const int bx  = blockIdx.x;

    // ---- tail blocks: zero padding rows ----
    if (bx >= GRID_GEMM) {
        const int p0 = (bx - GRID_GEMM) * ROWS_PER_Z;
        for (int i = tid; i < ROWS_PER_Z * (DIM / 4); i += NTHREADS) {
            int row = out_row_for_pad(p0 + (i >> 6));
            reinterpret_cast<float4*>(out + (size_t)row * DIM)[i & 63] =
                make_float4(0.f, 0.f, 0.f, 0.f);
        }
        return;
    }

    const int lane   = tid & 31;
    const int warpId = tid >> 5;
    const int warpM  = warpId & 1;      // 0..1 -> 32 rows each
    const int warpN  = warpId >> 1;     // 0..3 -> 64 cols each
    const int nb     = warpN * 64;
    const int gid    = lane >> 2;       // 0..7
    const int t4     = lane & 3;        // 0..3

    const int m0 = bx * BM;

    // A fill coords: row = tid>>2, chunks c = (tid&3)*4 + q (64B of the row)
    const int arow = tid >> 2;                // 0..63
    const int acb  = (tid & 3) * 4;           // chunk base 0,4,8,12
    const float* aP = A + (size_t)(m0 + arow) * PREV + acb * 4;
    int adst[4];
#pragma unroll
    for (int q = 0; q < 4; ++q) adst[q] = a_chunk_u32(arow, acb + q);

    const uint32_t asm_b = smem_u32_addr(AsBase);
    const uint32_t bsm_b = smem_u32_addr(BsBase);

    float acc[2][8][4];
#pragma unroll
    for (int mi = 0; mi < 2; ++mi)
#pragma unroll
        for (int ni = 0; ni < 8; ++ni)
#pragma unroll
            for (int j = 0; j < 4; ++j) acc[mi][ni][j] = 0.f;

    // ---- prologue: commit tile 0 (A + B in one group) ----
    {
#pragma unroll
        for (int q = 0; q < 4; ++q)
            CP_ASYNC16(asm_b + (uint32_t)adst[q] * 4, aP + q * 4);
#pragma unroll
        for (int i = 0; i < 8; ++i) {
            int c = tid + i * NTHREADS;      // 16B chunk 0..2047
            CP_ASYNC16(bsm_b + (uint32_t)c * 16, g_WH + c * 8);
        }
        CP_COMMIT();
    }

    for (int kt = 0; kt < KTILES; ++kt) {
        const int cur = kt & 1;
        const int nxt = cur ^ 1;

        CP_WAIT0();          // tile kt resident
        __syncthreads();     // all reads of stage nxt (tile kt-1) done

        // commit tile kt+1 into stage nxt (flies during compute of kt)
        if (kt + 1 < KTILES) {
            const float* aPn = aP + (kt + 1) * BK;
#pragma unroll
            for (int q = 0; q < 4; ++q)
                CP_ASYNC16(asm_b + (uint32_t)(nxt * A_STAGE + adst[q]) * 4, aPn + q * 4);
            const uint16_t* src = g_WH + (size_t)(kt + 1) * (2 * B_STAGE);
#pragma unroll
            for (int i = 0; i < 8; ++i) {
                int c = tid + i * NTHREADS;
                CP_ASYNC16(bsm_b + (uint32_t)(nxt * B_STAGE + c * 4) * 4, src + c * 8);
            }
            CP_COMMIT();
        }

        // ---- compute tile kt: 4 k-steps of 16 ----
        const uint32_t* As = AsBase + cur * A_STAGE;
        const uint32_t* Bs = BsBase + cur * B_STAGE;
#pragma unroll
        for (int kk = 0; kk < 4; ++kk) {
            // A fragments: float2 at ((kk*2+kh)*64 + row)*8 + t4*2, cvt at use
            uint32_t af[2][4];
#pragma unroll
            for (int mi = 0; mi < 2; ++mi) {
                const int r = warpM * 32 + mi * 16 + gid;
                float2 v00 = *reinterpret_cast<const float2*>(
                    As + ((kk * 2 + 0) * 64 + r) * 8 + t4 * 2);
                float2 v01 = *reinterpret_cast<const float2*>(
                    As + ((kk * 2 + 0) * 64 + r + 8) * 8 + t4 * 2);
                float2 v10 = *reinterpret_cast<const float2*>(
                    As + ((kk * 2 + 1) * 64 + r) * 8 + t4 * 2);
                float2 v11 = *reinterpret_cast<const float2*>(
                    As + ((kk * 2 + 1) * 64 + r + 8) * 8 + t4 * 2);
                af[mi][0] = h2_to_u32(v00.x, v00.y);
                af[mi][1] = h2_to_u32(v01.x, v01.y);
                af[mi][2] = h2_to_u32(v10.x, v10.y);
                af[mi][3] = h2_to_u32(v11.x, v11.y);
            }
            uint32_t bf[8][2];
#pragma unroll
            for (int ni = 0; ni < 8; ++ni) {
                int g = ((((kk * 4 + warpN) * 8 + ni) * 8 + gid) * 4 + t4) * 2;
                uint2 v = *reinterpret_cast<const uint2*>(Bs + g);
                bf[ni][0] = v.x; bf[ni][1] = v.y;
            }
#pragma unroll
            for (int ni = 0; ni < 8; ++ni) {
                mma_f16(acc[0][ni], af[0], bf[ni]);
                mma_f16(acc[1][ni], af[1], bf[ni]);
            }
        }
    }

    // ---- epilogue: bias + ragged scatter ----
    float2 bv[8];
#pragma unroll
    for (int ni = 0; ni < 8; ++ni)
        bv[ni] = *reinterpret_cast<const float2*>(bias + nb + ni * 8 + 2 * t4);

#pragma unroll
    for (int mi = 0; mi < 2; ++mi) {
        const int r0 = m0 + warpM * 32 + mi * 16 + gid;
        const int o0 = out_row_for_token(r0);
        const int o1 = out_row_for_token(r0 + 8);
        float* p0 = out + (size_t)o0 * DIM + nb + 2 * t4;
        float* p1 = out + (size_t)o1 * DIM + nb + 2 * t4;
#pragma unroll
        for (int ni = 0; ni < 8; ++ni) {
            float2 v0, v1;
            v0.x = acc[mi][ni][0] + bv[ni].x;
            v0.y = acc[mi][ni][1] + bv[ni].y;
            v1.x = acc[mi][ni][2] + bv[ni].x;
            v1.y = acc[mi][ni][3] + bv[ni].y;
            *reinterpret_cast<float2*>(p0 + ni * 8) = v0;
            *reinterpret_cast<float2*>(p1 + ni * 8) = v1;
        }
    }
}

extern "C" void kernel_launch(void* const* d_in, const int* in_sizes, int n_in,
                              void* d_out, int out_size) {
    const float* A    = (const float*)d_in[0];  // sent_embs [T_TOK, PREV]
    const float* W    = (const float*)d_in[1];  // [PREV, DIM]
    const float* bias = (const float*)d_in[2];  // [DIM]
    float* out = (float*)d_out;                 // [NDOCS*MAXLEN, DIM]

    cudaFuncSetAttribute(gemm_tc_scatter_kernel,
                         cudaFuncAttributeMaxDynamicSharedMemorySize, SMEM_BYTES);

    round_w_kernel<<<(PREV * DIM) / 256, 256>>>(W);
    gemm_tc_scatter_kernel<<<GRID_GEMM + ZBLOCKS, NTHREADS, SMEM_BYTES>>>(A, bias, out);
}

// round 13
// speedup vs baseline: 1.3028x; 1.3028x over previous
#include <cuda_runtime.h>
#include <cuda_fp16.h>
#include <cstdint>

// Problem constants (fixed by the reference: LENGTHS[i] = 1024 + 128*i, B=16)
#define T_TOK   31744
#define PREV    768
#define DIM     256
#define NDOCS   16
#define MAXLEN  2944

// GEMM tiling: CTA 64x256, 8 warps as 2(M) x 4(N), warp tile 32x64, fp16 k16
#define BM 64
#define BN 256
#define BK 64
#define NTHREADS 256
#define KTILES (PREV / BK)             // 12

// Fragment-major smem stages (u32 elements), fp16 data
#define A_STAGE 2048                   // 64x64 fp16 = 8 KB
#define B_STAGE 8192                   // 64x256 fp16 = 32 KB
#define SMEM_BYTES ((2 * A_STAGE + 2 * B_STAGE) * 4)   // 81920 B -> 2 CTAs/SM

#define GRID_GEMM (T_TOK / BM)         // 496
#define PAD_ROWS  (NDOCS * MAXLEN - T_TOK)  // 15360
#define ZBLOCKS   120
#define ROWS_PER_Z (PAD_ROWS / ZBLOCKS)     // 128

// W pre-converted to fp16, fragment-major per 64-k tile (16384 halves/tile)
__device__ uint16_t g_WH[PREV * DIM];

// ---------------- helpers ----------------
__device__ __forceinline__ int doc_offset(int b) { return 1024 * b + 64 * b * (b - 1); }
__device__ __forceinline__ int pad_offset(int b) { return 1920 * b - 64 * b * (b - 1); }

__device__ __forceinline__ int out_row_for_token(int t) {
    int b = 0;
#pragma unroll
    for (int i = 1; i < NDOCS; ++i) if (t >= doc_offset(i)) b = i;
    return b * MAXLEN + (t - doc_offset(b));
}
__device__ __forceinline__ int out_row_for_pad(int p) {
    int b = 0;
#pragma unroll
    for (int i = 1; i < NDOCS; ++i) if (p >= pad_offset(i)) b = i;
    return b * MAXLEN + (1024 + 128 * b) + (p - pad_offset(b));
}

__device__ __forceinline__ uint32_t smem_u32_addr(const void* p) {
    uint32_t a;
    asm("{ .reg .u64 t; cvta.to.shared.u64 t, %1; cvt.u32.u64 %0, t; }" : "=r"(a) : "l"(p));
    return a;
}

__device__ __forceinline__ void mma_f16(float* d, const uint32_t* a, const uint32_t* b) {
    asm volatile(
        "mma.sync.aligned.m16n8k16.row.col.f32.f16.f16.f32 "
        "{%0,%1,%2,%3}, {%4,%5,%6,%7}, {%8,%9}, {%0,%1,%2,%3};"
        : "+f"(d[0]), "+f"(d[1]), "+f"(d[2]), "+f"(d[3])
        : "r"(a[0]), "r"(a[1]), "r"(a[2]), "r"(a[3]), "r"(b[0]), "r"(b[1]));
}

#define CP_ASYNC16(dst_u32, src_ptr) \
    asm volatile("cp.async.cg.shared.global [%0], [%1], 16;" \
                 :: "r"(dst_u32), "l"(src_ptr) : "memory")
#define CP_COMMIT() asm volatile("cp.async.commit_group;" ::: "memory")
#define CP_WAIT0()  asm volatile("cp.async.wait_group 0;" ::: "memory")

__device__ __forceinline__ uint32_t h2u(float x, float y) {
    __half2 h = __float22half2_rn(make_float2(x, y));
    return *reinterpret_cast<uint32_t*>(&h);
}

// B fragment-major HALF index within one 64x256 K-tile (16384 halves)
__host__ __device__ __forceinline__ int b_frag_half(int n, int kl) {
    int warpN = n >> 6, ni = (n >> 3) & 7, gid = n & 7;
    int kk = kl >> 4, k16 = kl & 15;
    int reg = k16 >> 3, t4 = (k16 & 7) >> 1, half = k16 & 1;
    int u32idx = ((((kk * 4 + warpN) * 8 + ni) * 8 + gid) * 4 + t4) * 2 + reg;
    return u32idx * 2 + half;
}

// ---------------- W convert + permute kernel (tiny, one-time) ----------------
__global__ void round_w_kernel(const float* __restrict__ W) {
    int i = blockIdx.x * 256 + threadIdx.x;     // over PREV*DIM
    int k = i / DIM, n = i - k * DIM;
    int kt = k >> 6, kl = k & 63;
    __half h = __float2half_rn(W[i]);
    g_WH[kt * (2 * B_STAGE) + b_frag_half(n, kl)] = __half_as_ushort(h);
}

// Store one 32-k A half (2 float4 = 8 k values) into fragment-major smem.
// Thread covers row ar at k offset (tid&3)*8 within the half; half s adds kk+=2*s.
__device__ __forceinline__ void sts_A(uint32_t* Asn, int tid, int s,
                                      const float4& p0, const float4& p1) {
    const int ar  = tid >> 2;
    const int f   = tid & 3;
    const int kk  = s * 2 + (f >> 1);
    const int khi = f & 1;
    const int gid = ar & 7;
    const int base = (((kk * 2 + (ar >> 5)) * 2 + ((ar >> 4) & 1)) * 8 + gid) * 16
                     + khi * 2 + ((ar >> 3) & 1);
    const int x = (gid & 3) ^ kk;
    Asn[base + ((0 ^ x) & 3) * 4] = h2u(p0.x, p0.y);
    Asn[base + ((1 ^ x) & 3) * 4] = h2u(p0.z, p0.w);
    Asn[base + ((2 ^ x) & 3) * 4] = h2u(p1.x, p1.y);
    Asn[base + ((3 ^ x) & 3) * 4] = h2u(p1.z, p1.w);
}

// ---------------- main fused kernel ----------------
__global__ __launch_bounds__(NTHREADS, 2)
void gemm_tc_scatter_kernel(const float* __restrict__ A,
                            const float* __restrict__ bias,
                            float* __restrict__ out) {
    extern __shared__ uint32_t sm[];
    uint32_t* AsBase = sm;                    // [2][A_STAGE] fp16 fragment-major
    uint32_t* BsBase = sm + 2 * A_STAGE;      // [2][B_STAGE] fp16 fragment-major

    const int tid = threadIdx.x;
    const int bx  = blockIdx.x;

    // ---- tail blocks: zero padding rows ----
    if (bx >= GRID_GEMM) {
        const int p0 = (bx - GRID_GEMM) * ROWS_PER_Z;
        for (int i = tid; i < ROWS_PER_Z * (DIM / 4); i += NTHREADS) {
            int row = out_row_for_pad(p0 + (i >> 6));
            reinterpret_cast<float4*>(out + (size_t)row * DIM)[i & 63] =
                make_float4(0.f, 0.f, 0.f, 0.f);
        }
        return;
    }

    const int lane   = tid & 31;
    const int warpId = tid >> 5;
    const int warpM  = warpId & 1;      // 0..1 -> 32 rows each
    const int warpN  = warpId >> 1;     // 0..3 -> 64 cols each
    const int nb     = warpN * 64;
    const int gid    = lane >> 2;       // 0..7
    const int t4     = lane & 3;        // 0..3

    const int m0 = bx * BM;

    // A fill base: row ar = tid>>2, k offset (tid&3)*8 within each 32-k half
    const float* aP = A + (size_t)(m0 + (tid >> 2)) * PREV + (tid & 3) * 8;

    const uint32_t bsm = smem_u32_addr(BsBase);

    float acc[2][8][4];
#pragma unroll
    for (int mi = 0; mi < 2; ++mi)
#pragma unroll
        for (int ni = 0; ni < 8; ++ni)
#pragma unroll
            for (int j = 0; j < 4; ++j) acc[mi][ni][j] = 0.f;

    float4 pa0, pa1;

    // ---- prologue: fill A(0) fully, commit B(0); prefetch A(1) sub0 ----
    {
        pa0 = *reinterpret_cast<const float4*>(aP);
        pa1 = *reinterpret_cast<const float4*>(aP + 4);
        sts_A(AsBase, tid, 0, pa0, pa1);
        pa0 = *reinterpret_cast<const float4*>(aP + 32);
        pa1 = *reinterpret_cast<const float4*>(aP + 36);
        sts_A(AsBase, tid, 1, pa0, pa1);
#pragma unroll
        for (int i = 0; i < 8; ++i) {
            int c = tid + i * NTHREADS;      // 16B chunk 0..2047
            CP_ASYNC16(bsm + (uint32_t)c * 16, g_WH + c * 8);
        }
        CP_COMMIT();
        // prefetch A(1) sub0
        pa0 = *reinterpret_cast<const float4*>(aP + BK);
        pa1 = *reinterpret_cast<const float4*>(aP + BK + 4);
    }

    for (int kt = 0; kt < KTILES; ++kt) {
        const int cur = kt & 1;
        const int nxt = cur ^ 1;
        const bool more = (kt + 1 < KTILES);

        CP_WAIT0();          // B(kt) resident
        __syncthreads();     // fills visible; stage nxt free of readers

        // commit B(kt+1) (full tile of compute to land)
        if (more) {
            const uint16_t* src = g_WH + (size_t)(kt + 1) * (2 * B_STAGE);
#pragma unroll
            for (int i = 0; i < 8; ++i) {
                int c = tid + i * NTHREADS;
                CP_ASYNC16(bsm + (uint32_t)(nxt * B_STAGE + c * 4) * 4, src + c * 8);
            }
            CP_COMMIT();
        }

        const uint32_t* As = AsBase + cur * A_STAGE;
        const uint32_t* Bs = BsBase + cur * B_STAGE;

        // ---- compute kk = 0,1 ----
#pragma unroll
        for (int kk = 0; kk < 2; ++kk) {
            uint32_t af[2][4];
#pragma unroll
            for (int mi = 0; mi < 2; ++mi) {
                int g = ((((kk * 2 + warpM) * 2 + mi) * 8 + gid) * 4 +
                         ((t4 ^ (gid & 3) ^ kk) & 3)) * 4;
                uint4 v = *reinterpret_cast<const uint4*>(As + g);
                af[mi][0] = v.x; af[mi][1] = v.y; af[mi][2] = v.z; af[mi][3] = v.w;
            }
            uint32_t bf[8][2];
#pragma unroll
            for (int ni = 0; ni < 8; ++ni) {
                int g = ((((kk * 4 + warpN) * 8 + ni) * 8 + gid) * 4 + t4) * 2;
                uint2 v = *reinterpret_cast<const uint2*>(Bs + g);
                bf[ni][0] = v.x; bf[ni][1] = v.y;
            }
#pragma unroll
            for (int ni = 0; ni < 8; ++ni) {
                mma_f16(acc[0][ni], af[0], bf[ni]);
                mma_f16(acc[1][ni], af[1], bf[ni]);
            }
        }

        // ---- mid: STS A(kt+1) sub0 (held in pa), LDG A(kt+1) sub1 ----
        if (more) {
            sts_A(AsBase + nxt * A_STAGE, tid, 0, pa0, pa1);
            const float* p = aP + (kt + 1) * BK + 32;
            pa0 = *reinterpret_cast<const float4*>(p);
            pa1 = *reinterpret_cast<const float4*>(p + 4);
        }

        // ---- compute kk = 2,3 ----
#pragma unroll
        for (int kk = 2; kk < 4; ++kk) {
            uint32_t af[2][4];
#pragma unroll
            for (int mi = 0; mi < 2; ++mi) {
                int g = ((((kk * 2 + warpM) * 2 + mi) * 8 + gid) * 4 +
                         ((t4 ^ (gid & 3) ^ kk) & 3)) * 4;
                uint4 v = *reinterpret_cast<const uint4*>(As + g);
                af[mi][0] = v.x; af[mi][1] = v.y; af[mi][2] = v.z; af[mi][3] = v.w;
            }
            uint32_t bf[8][2];
#pragma unroll
            for (int ni = 0; ni < 8; ++ni) {
                int g = ((((kk * 4 + warpN) * 8 + ni) * 8 + gid) * 4 + t4) * 2;
                uint2 v = *reinterpret_cast<const uint2*>(Bs + g);
                bf[ni][0] = v.x; bf[ni][1] = v.y;
            }
#pragma unroll
            for (int ni = 0; ni < 8; ++ni) {
                mma_f16(acc[0][ni], af[0], bf[ni]);
                mma_f16(acc[1][ni], af[1], bf[ni]);
            }
        }

        // ---- end: STS A(kt+1) sub1, LDG A(kt+2) sub0 ----
        if (more) {
            sts_A(AsBase + nxt * A_STAGE, tid, 1, pa0, pa1);
            if (kt + 2 < KTILES) {
                const float* p = aP + (kt + 2) * BK;
                pa0 = *reinterpret_cast<const float4*>(p);
                pa1 = *reinterpret_cast<const float4*>(p + 4);
            }
        }
    }

    // ---- epilogue: bias + ragged scatter ----
    float2 bv[8];
#pragma unroll
    for (int ni = 0; ni < 8; ++ni)
        bv[ni] = *reinterpret_cast<const float2*>(bias + nb + ni * 8 + 2 * t4);

#pragma unroll
    for (int mi = 0; mi < 2; ++mi) {
        const int r0 = m0 + warpM * 32 + mi * 16 + gid;
        const int o0 = out_row_for_token(r0);
        const int o1 = out_row_for_token(r0 + 8);
        float* p0 = out + (size_t)o0 * DIM + nb + 2 * t4;
        float* p1 = out + (size_t)o1 * DIM + nb + 2 * t4;
#pragma unroll
        for (int ni = 0; ni < 8; ++ni) {
            float2 v0, v1;
            v0.x = acc[mi][ni][0] + bv[ni].x;
            v0.y = acc[mi][ni][1] + bv[ni].y;
            v1.x = acc[mi][ni][2] + bv[ni].x;
            v1.y = acc[mi][ni][3] + bv[ni].y;
            *reinterpret_cast<float2*>(p0 + ni * 8) = v0;
            *reinterpret_cast<float2*>(p1 + ni * 8) = v1;
        }
    }
}

extern "C" void kernel_launch(void* const* d_in, const int* in_sizes, int n_in,
                              void* d_out, int out_size) {
    const float* A    = (const float*)d_in[0];  // sent_embs [T_TOK, PREV]
    const float* W    = (const float*)d_in[1];  // [PREV, DIM]
    const float* bias = (const float*)d_in[2];  // [DIM]
    float* out = (float*)d_out;                 // [NDOCS*MAXLEN, DIM]

    cudaFuncSetAttribute(gemm_tc_scatter_kernel,
                         cudaFuncAttributeMaxDynamicSharedMemorySize, SMEM_BYTES);

    round_w_kernel<<<(PREV * DIM) / 256, 256>>>(W);
    gemm_tc_scatter_kernel<<<GRID_GEMM + ZBLOCKS, NTHREADS, SMEM_BYTES>>>(A, bias, out);
}